// round 11
// baseline (speedup 1.0000x reference)
#include <cuda_runtime.h>
#include <math.h>
#include <stdint.h>

// Problem constants
#define TT   2048
#define BB   32
#define ICC  512
#define HCC  512
#define LLL  2

// Recurrence: cluster = 8 CTAs = one batch group (2 batches); CTA owns 64 ch.
#define CSIZE 8
#define NCTA  128
#define RTH   256
#define BPG   2
#define CPG   64

// Projection GEMM config
#define PBM 128
#define PBN 128
#define PBK 16
#define PLD (PBM + 4)

// ---------------------------------------------------------------------------
// Scratch (static device globals: allocation-free per harness rules)
// ---------------------------------------------------------------------------
__device__ float g_xproj[(size_t)TT * BB * HCC];
__device__ float g_ys0[(size_t)TT * BB * HCC];

// ---------------------------------------------------------------------------
// Cluster / mbarrier helpers
// ---------------------------------------------------------------------------
__device__ __forceinline__ uint32_t smem_u32(const void* p) {
    uint32_t a;
    asm("{ .reg .u64 t; cvta.to.shared.u64 t, %1; cvt.u32.u64 %0, t; }"
        : "=r"(a) : "l"(p));
    return a;
}
__device__ __forceinline__ uint32_t mapa_u32(uint32_t a, uint32_t rank) {
    uint32_t r;
    asm("mapa.shared::cluster.u32 %0, %1, %2;" : "=r"(r) : "r"(a), "r"(rank));
    return r;
}
__device__ __forceinline__ void st_cluster_f4(uint32_t a, float4 v) {
    asm volatile("st.shared::cluster.v4.f32 [%0], {%1,%2,%3,%4};"
                 :: "r"(a), "f"(v.x), "f"(v.y), "f"(v.z), "f"(v.w) : "memory");
}
__device__ __forceinline__ void mbar_init(uint32_t a, uint32_t cnt) {
    asm volatile("mbarrier.init.shared.b64 [%0], %1;" :: "r"(a), "r"(cnt) : "memory");
}
__device__ __forceinline__ void mbar_arrive_remote(uint32_t a) {
    // a is already mapa'd into the target CTA's shared space.
    asm volatile("mbarrier.arrive.release.cluster.shared::cluster.b64 _, [%0];"
                 :: "r"(a) : "memory");
}
__device__ __forceinline__ void mbar_wait_parity(uint32_t a, uint32_t parity) {
    uint32_t done;
    asm volatile(
        "{\n\t.reg .pred p;\n\t"
        "mbarrier.try_wait.parity.acquire.cluster.shared::cta.b64 p, [%1], %2;\n\t"
        "selp.b32 %0, 1, 0, p;\n\t}"
        : "=r"(done) : "r"(a), "r"(parity) : "memory");
    if (!done) {
        asm volatile(
            "{\n\t.reg .pred P1;\n\t"
            "W_%=:\n\t"
            "mbarrier.try_wait.parity.acquire.cluster.shared::cta.b64 P1, [%0], %1, 0x989680;\n\t"
            "@P1 bra.uni D_%=;\n\t"
            "bra.uni W_%=;\n\t"
            "D_%=:\n\t}"
            :: "r"(a), "r"(parity) : "memory");
    }
}
#define CL_SYNC() do { \
    asm volatile("barrier.cluster.arrive.aligned;" ::: "memory"); \
    asm volatile("barrier.cluster.wait.aligned;"   ::: "memory"); } while (0)

// ---------------------------------------------------------------------------
// Projection GEMM (unchanged, proven): C[row,n] = A[row,:] . W[n,:] + b[n]
// ---------------------------------------------------------------------------
__global__ __launch_bounds__(256, 2)
void proj_kernel(const float* __restrict__ Xin, const float* __restrict__ Wp,
                 const float* __restrict__ bp, int use_internal)
{
    const float* A = use_internal ? (const float*)g_ys0 : Xin;
    __shared__ float As[PBK][PLD];
    __shared__ float Bs[PBK][PLD];

    const int t  = threadIdx.x;
    const int m0 = blockIdx.y * PBM;
    const int n0 = blockIdx.x * PBN;
    const int lr = t >> 1;
    const int lc = (t & 1) << 3;
    const int tx = t & 15;
    const int ty = t >> 4;

    float acc[8][8];
#pragma unroll
    for (int i = 0; i < 8; i++)
#pragma unroll
        for (int j = 0; j < 8; j++) acc[i][j] = 0.f;

    const float* Ag = A  + (size_t)(m0 + lr) * ICC;
    const float* Bg = Wp + (size_t)(n0 + lr) * ICC;

    for (int k0 = 0; k0 < ICC; k0 += PBK) {
        float4 a0 = __ldg((const float4*)(Ag + k0 + lc));
        float4 a1 = __ldg((const float4*)(Ag + k0 + lc + 4));
        float4 b0 = __ldg((const float4*)(Bg + k0 + lc));
        float4 b1 = __ldg((const float4*)(Bg + k0 + lc + 4));
        As[lc+0][lr] = a0.x; As[lc+1][lr] = a0.y; As[lc+2][lr] = a0.z; As[lc+3][lr] = a0.w;
        As[lc+4][lr] = a1.x; As[lc+5][lr] = a1.y; As[lc+6][lr] = a1.z; As[lc+7][lr] = a1.w;
        Bs[lc+0][lr] = b0.x; Bs[lc+1][lr] = b0.y; Bs[lc+2][lr] = b0.z; Bs[lc+3][lr] = b0.w;
        Bs[lc+4][lr] = b1.x; Bs[lc+5][lr] = b1.y; Bs[lc+6][lr] = b1.z; Bs[lc+7][lr] = b1.w;
        __syncthreads();
#pragma unroll
        for (int k = 0; k < PBK; k++) {
            float4 am0 = *(const float4*)&As[k][ty * 8];
            float4 am1 = *(const float4*)&As[k][ty * 8 + 4];
            float4 bn0 = *(const float4*)&Bs[k][tx * 8];
            float4 bn1 = *(const float4*)&Bs[k][tx * 8 + 4];
            float am[8] = {am0.x, am0.y, am0.z, am0.w, am1.x, am1.y, am1.z, am1.w};
            float bn[8] = {bn0.x, bn0.y, bn0.z, bn0.w, bn1.x, bn1.y, bn1.z, bn1.w};
#pragma unroll
            for (int i = 0; i < 8; i++)
#pragma unroll
                for (int j = 0; j < 8; j++)
                    acc[i][j] = fmaf(am[i], bn[j], acc[i][j]);
        }
        __syncthreads();
    }

    float4 bv0 = __ldg((const float4*)(bp + n0 + tx * 8));
    float4 bv1 = __ldg((const float4*)(bp + n0 + tx * 8 + 4));
#pragma unroll
    for (int i = 0; i < 8; i++) {
        size_t row = (size_t)(m0 + ty * 8 + i);
        float4 o0 = make_float4(acc[i][0] + bv0.x, acc[i][1] + bv0.y,
                                acc[i][2] + bv0.z, acc[i][3] + bv0.w);
        float4 o1 = make_float4(acc[i][4] + bv1.x, acc[i][5] + bv1.y,
                                acc[i][6] + bv1.z, acc[i][7] + bv1.w);
        *(float4*)&g_xproj[row * HCC + n0 + tx * 8]     = o0;
        *(float4*)&g_xproj[row * HCC + n0 + tx * 8 + 4] = o1;
    }
}

// ---------------------------------------------------------------------------
// Recurrence, push edition. Cluster rank = cg (0..7). CTA(bg,cg):
// batches {2bg,2bg+1}, channels [64cg, 64cg+64).
//  - Wh slice in registers (32 float4/thread, step-invariant).
//  - h staging hs[2][1024] is WRITTEN BY PRODUCERS via st.shared::cluster:
//    warp 0's epilogue (32 threads x 4 channels) pushes its float4 to all 8
//    ranks' hs[next] and release-arrives on each rank's mbarrier (32 arrives
//    per source per target -> expect 256).
//  - Consumers: mbarrier.try_wait.parity.acquire.cluster (~60-90 cyc wakeup),
//    data already local. Double buffer + parity gives backpressure: a CTA
//    can only overwrite buffer b after receiving all step-(s+1) arrives, each
//    of which follows that peer's completed reads of buffer b at step s.
// ---------------------------------------------------------------------------
__global__ __launch_bounds__(RTH, 1) __cluster_dims__(CSIZE, 1, 1)
void rec_kernel(const float* __restrict__ Wh, const float* __restrict__ bh,
                float* __restrict__ out_ys, float* __restrict__ out_hs,
                int write_internal)
{
    __shared__ float hs[2][BPG * HCC];          // staged h, double buffered (8 KB)
    __shared__ float red[4 * 128];              // k-split partials
    __shared__ __align__(8) unsigned long long mbar[2];

    const int t    = threadIdx.x;
    const int bid  = blockIdx.x;
    const int bg   = bid >> 3;
    const int cg   = bid & 7;
    const int b0   = bg * BPG;
    const int c0   = cg * CPG;
    const int w    = t >> 5;
    const int lane = t & 31;
    const int ks   = w >> 1;                    // k-slice 0..3 (128 k each)
    const int c    = ((w & 1) << 5) + lane;     // channel-in-group 0..63

    float* ysp = write_internal ? (float*)g_ys0 : out_ys;

    // Step-invariant weights -> registers (32 float4).
    float4 wr[32];
    {
        const float4* wsrc = (const float4*)(Wh + (size_t)(c0 + c) * HCC + ks * 128);
#pragma unroll
        for (int j = 0; j < 32; j++) wr[j] = __ldg(wsrc + j);
    }

    const uint32_t mb0  = smem_u32(&mbar[0]);
    const uint32_t mb1  = smem_u32(&mbar[1]);
    const uint32_t hsb0 = smem_u32(&hs[0][0]);
    const uint32_t hsb1 = smem_u32(&hs[1][0]);

    if (t == 0) { mbar_init(mb0, 256); mbar_init(mb1, 256); }
    // Zero step-0 staging buffer locally (h0 = 0 everywhere; no comm needed).
#pragma unroll
    for (int i = t; i < BPG * HCC; i += RTH) hs[0][i] = 0.f;
    __syncthreads();
    CL_SYNC();   // mbarriers init'd cluster-wide before any push can land

    // Epilogue lane setup (warp 0 only): u = lane, b = u>>4, cq = u&15,
    // owns channels c0+4cq .. +3 of batch b0+b.
    const int  eb   = lane >> 4;
    const int  ecq  = lane & 15;
    const uint32_t doff = (uint32_t)((eb * HCC + c0 + 4 * ecq) * 4);  // byte off in hs[buf]
    float4 bq = make_float4(0, 0, 0, 0);
    if (w == 0) bq = __ldg((const float4*)(bh + c0 + 4 * ecq));

    int ph0 = 0, ph1 = 0;

    for (int s = 0; s < TT; s++) {
        // Prefetch xproj (warp 0 only; issued before the wait).
        float4 xq = make_float4(0, 0, 0, 0);
        if (w == 0)
            xq = __ldg((const float4*)(g_xproj + (size_t)s * (BB * HCC) +
                                       (size_t)(b0 + eb) * HCC + c0 + 4 * ecq));

        if (s > 0) {
            if (s & 1) { mbar_wait_parity(mb1, (uint32_t)ph1); ph1 ^= 1; }
            else       { mbar_wait_parity(mb0, (uint32_t)ph0); ph0 ^= 1; }
        }

        // Dot: channel c fixed, k in [128ks, 128ks+128), both batches.
        const float4* hb = (const float4*)hs[s & 1] + (ks << 5);
        float a0 = 0.f, a1 = 0.f;
#pragma unroll
        for (int j = 0; j < 32; j++) {
            float4 wv = wr[j];
            float4 h0 = hb[j];
            float4 h1 = hb[128 + j];
            a0 = fmaf(wv.x, h0.x, a0); a0 = fmaf(wv.y, h0.y, a0);
            a0 = fmaf(wv.z, h0.z, a0); a0 = fmaf(wv.w, h0.w, a0);
            a1 = fmaf(wv.x, h1.x, a1); a1 = fmaf(wv.y, h1.y, a1);
            a1 = fmaf(wv.z, h1.z, a1); a1 = fmaf(wv.w, h1.w, a1);
        }
        red[(ks << 7) + c]      = a0;
        red[(ks << 7) + 64 + c] = a1;
        __syncthreads();

        // Epilogue + push: warp 0, 32 threads x 4 channels.
        if (w == 0) {
            const float4* r4 = (const float4*)red;
            float4 sum = make_float4(xq.x + bq.x, xq.y + bq.y,
                                     xq.z + bq.z, xq.w + bq.w);
#pragma unroll
            for (int k = 0; k < 4; k++) {
                float4 rv = r4[(k << 5) + lane];
                sum.x += rv.x; sum.y += rv.y; sum.z += rv.z; sum.w += rv.w;
            }
            float4 hn = make_float4(tanhf(sum.x), tanhf(sum.y),
                                    tanhf(sum.z), tanhf(sum.w));

            *(float4*)(ysp + (size_t)s * (BB * HCC) +
                       (size_t)(b0 + eb) * HCC + c0 + 4 * ecq) = hn;
            if (s == TT - 1)
                *(float4*)(out_hs + (size_t)(b0 + eb) * HCC + c0 + 4 * ecq) = hn;

            if (s + 1 < TT) {
                const uint32_t hl = ((s + 1) & 1 ? hsb1 : hsb0) + doff;
                const uint32_t ml = ((s + 1) & 1 ? mb1  : mb0);
#pragma unroll
                for (int r = 0; r < CSIZE; r++)
                    st_cluster_f4(mapa_u32(hl, (uint32_t)r), hn);
#pragma unroll
                for (int r = 0; r < CSIZE; r++)
                    mbar_arrive_remote(mapa_u32(ml, (uint32_t)r));
            }
        }
        // No trailing syncthreads: warps 1-7 block on the next mbarrier wait,
        // which cannot complete before warp 0 (which reads red first) arrives.
    }

    CL_SYNC();   // no CTA exits while peers' pushes may still be in flight
}

// ---------------------------------------------------------------------------
// Output layout: [hs (L,B,HC) | inp (T,B,HC)]
// ---------------------------------------------------------------------------
extern "C" void kernel_launch(void* const* d_in, const int* in_sizes, int n_in,
                              void* d_out, int out_size) {
    const float* x  = (const float*)d_in[0];
    const float* Wi = (const float*)d_in[1];
    const float* bi = (const float*)d_in[2];
    const float* Wh = (const float*)d_in[3];
    const float* bh = (const float*)d_in[4];
    float* out = (float*)d_out;

    dim3 pg(HCC / PBN, (TT * BB) / PBM);  // (4, 512)

    // Layer 0
    proj_kernel<<<pg, 256>>>(x, Wi, bi, 0);
    rec_kernel<<<NCTA, RTH>>>(Wh, bh, nullptr, out, 1);

    // Layer 1
    proj_kernel<<<pg, 256>>>(x, Wi + HCC * ICC, bi + HCC, 1);
    rec_kernel<<<NCTA, RTH>>>(Wh + HCC * HCC, bh + HCC,
                              out + (size_t)LLL * BB * HCC,  // inp region
                              out + BB * HCC,                // hs[1]
                              0);
}

// round 12
// speedup vs baseline: 1.6172x; 1.6172x over previous
#include <cuda_runtime.h>
#include <math.h>
#include <stdint.h>

// Problem constants
#define TT   2048
#define BB   32
#define ICC  512
#define HCC  512
#define LLL  2

// Recurrence: cluster = 8 CTAs = one batch group (2 batches); CTA owns 64 ch.
#define CSIZE 8
#define NCTA  128
#define RTH   256
#define BPG   2
#define CPG   64

// Projection GEMM config
#define PBM 128
#define PBN 128
#define PBK 16
#define PLD (PBM + 4)

// ---------------------------------------------------------------------------
// Scratch (static device globals: allocation-free per harness rules)
// ---------------------------------------------------------------------------
__device__ float g_xproj[(size_t)TT * BB * HCC];
__device__ float g_ys0[(size_t)TT * BB * HCC];

// ---------------------------------------------------------------------------
// Packed f32x2 helpers (FFMA2: ptxas never auto-fuses; PTX-only pattern)
// ---------------------------------------------------------------------------
__device__ __forceinline__ void fma2(unsigned long long& acc,
                                     unsigned long long a, unsigned long long b) {
    asm("fma.rn.f32x2 %0, %1, %2, %0;" : "+l"(acc) : "l"(a), "l"(b));
}
__device__ __forceinline__ unsigned long long dup2(float x) {
    unsigned long long d;
    asm("mov.b64 %0, {%1, %1};" : "=l"(d) : "f"(x));
    return d;
}
__device__ __forceinline__ unsigned long long add2(unsigned long long a,
                                                   unsigned long long b) {
    unsigned long long r;
    asm("add.rn.f32x2 %0, %1, %2;" : "=l"(r) : "l"(a), "l"(b));
    return r;
}
__device__ __forceinline__ float2 unpk(unsigned long long v) {
    float2 r;
    asm("mov.b64 {%0, %1}, %2;" : "=f"(r.x), "=f"(r.y) : "l"(v));
    return r;
}

// ---------------------------------------------------------------------------
// Cluster / mbarrier helpers (all field-verified in earlier rounds)
// ---------------------------------------------------------------------------
__device__ __forceinline__ uint32_t smem_u32(const void* p) {
    uint32_t a;
    asm("{ .reg .u64 t; cvta.to.shared.u64 t, %1; cvt.u32.u64 %0, t; }"
        : "=r"(a) : "l"(p));
    return a;
}
__device__ __forceinline__ uint32_t mapa_u32(uint32_t a, uint32_t rank) {
    uint32_t r;
    asm("mapa.shared::cluster.u32 %0, %1, %2;" : "=r"(r) : "r"(a), "r"(rank));
    return r;
}
__device__ __forceinline__ void st_cluster_f4(uint32_t a, float4 v) {
    asm volatile("st.shared::cluster.v4.f32 [%0], {%1,%2,%3,%4};"
                 :: "r"(a), "f"(v.x), "f"(v.y), "f"(v.z), "f"(v.w) : "memory");
}
__device__ __forceinline__ void mbar_init(uint32_t a, uint32_t cnt) {
    asm volatile("mbarrier.init.shared.b64 [%0], %1;" :: "r"(a), "r"(cnt) : "memory");
}
__device__ __forceinline__ void mbar_arrive_remote(uint32_t a) {
    asm volatile("mbarrier.arrive.release.cluster.shared::cluster.b64 _, [%0];"
                 :: "r"(a) : "memory");
}
__device__ __forceinline__ void mbar_wait_parity(uint32_t a, uint32_t parity) {
    uint32_t done;
    asm volatile(
        "{\n\t.reg .pred p;\n\t"
        "mbarrier.try_wait.parity.acquire.cluster.shared::cta.b64 p, [%1], %2;\n\t"
        "selp.b32 %0, 1, 0, p;\n\t}"
        : "=r"(done) : "r"(a), "r"(parity) : "memory");
    if (!done) {
        asm volatile(
            "{\n\t.reg .pred P1;\n\t"
            "W_%=:\n\t"
            "mbarrier.try_wait.parity.acquire.cluster.shared::cta.b64 P1, [%0], %1, 0x989680;\n\t"
            "@P1 bra.uni D_%=;\n\t"
            "bra.uni W_%=;\n\t"
            "D_%=:\n\t}"
            :: "r"(a), "r"(parity) : "memory");
    }
}
#define CL_SYNC() do { \
    asm volatile("barrier.cluster.arrive.aligned;" ::: "memory"); \
    asm volatile("barrier.cluster.wait.aligned;"   ::: "memory"); } while (0)

// ---------------------------------------------------------------------------
// Projection GEMM with packed FFMA2: C[row,n] = A[row,:] . W[n,:] + b[n]
// Same 128x128x16 tiling as the proven version; inner product packs n-pairs
// into f32x2 accumulators (8 dup movs + 32 FFMA2 per k instead of 64 FFMA).
// ---------------------------------------------------------------------------
__global__ __launch_bounds__(256, 2)
void proj_kernel(const float* __restrict__ Xin, const float* __restrict__ Wp,
                 const float* __restrict__ bp, int use_internal)
{
    const float* A = use_internal ? (const float*)g_ys0 : Xin;
    __shared__ float As[PBK][PLD];
    __shared__ float Bs[PBK][PLD];

    const int t  = threadIdx.x;
    const int m0 = blockIdx.y * PBM;
    const int n0 = blockIdx.x * PBN;
    const int lr = t >> 1;
    const int lc = (t & 1) << 3;
    const int tx = t & 15;
    const int ty = t >> 4;

    unsigned long long acc2[8][4];   // [m][n-pair], f32x2 packed
#pragma unroll
    for (int i = 0; i < 8; i++)
#pragma unroll
        for (int j = 0; j < 4; j++) acc2[i][j] = 0ULL;

    const float* Ag = A  + (size_t)(m0 + lr) * ICC;
    const float* Bg = Wp + (size_t)(n0 + lr) * ICC;

    for (int k0 = 0; k0 < ICC; k0 += PBK) {
        float4 a0 = __ldg((const float4*)(Ag + k0 + lc));
        float4 a1 = __ldg((const float4*)(Ag + k0 + lc + 4));
        float4 b0 = __ldg((const float4*)(Bg + k0 + lc));
        float4 b1 = __ldg((const float4*)(Bg + k0 + lc + 4));
        As[lc+0][lr] = a0.x; As[lc+1][lr] = a0.y; As[lc+2][lr] = a0.z; As[lc+3][lr] = a0.w;
        As[lc+4][lr] = a1.x; As[lc+5][lr] = a1.y; As[lc+6][lr] = a1.z; As[lc+7][lr] = a1.w;
        Bs[lc+0][lr] = b0.x; Bs[lc+1][lr] = b0.y; Bs[lc+2][lr] = b0.z; Bs[lc+3][lr] = b0.w;
        Bs[lc+4][lr] = b1.x; Bs[lc+5][lr] = b1.y; Bs[lc+6][lr] = b1.z; Bs[lc+7][lr] = b1.w;
        __syncthreads();
#pragma unroll
        for (int k = 0; k < PBK; k++) {
            float4 am0 = *(const float4*)&As[k][ty * 8];
            float4 am1 = *(const float4*)&As[k][ty * 8 + 4];
            ulonglong2 bu0 = *(const ulonglong2*)&Bs[k][tx * 8];      // (n0n1),(n2n3)
            ulonglong2 bu1 = *(const ulonglong2*)&Bs[k][tx * 8 + 4];  // (n4n5),(n6n7)
            float am[8] = {am0.x, am0.y, am0.z, am0.w, am1.x, am1.y, am1.z, am1.w};
#pragma unroll
            for (int i = 0; i < 8; i++) {
                unsigned long long ad = dup2(am[i]);
                fma2(acc2[i][0], ad, bu0.x);
                fma2(acc2[i][1], ad, bu0.y);
                fma2(acc2[i][2], ad, bu1.x);
                fma2(acc2[i][3], ad, bu1.y);
            }
        }
        __syncthreads();
    }

    float4 bv0 = __ldg((const float4*)(bp + n0 + tx * 8));
    float4 bv1 = __ldg((const float4*)(bp + n0 + tx * 8 + 4));
#pragma unroll
    for (int i = 0; i < 8; i++) {
        size_t row = (size_t)(m0 + ty * 8 + i);
        float2 p0 = unpk(acc2[i][0]);
        float2 p1 = unpk(acc2[i][1]);
        float2 p2 = unpk(acc2[i][2]);
        float2 p3 = unpk(acc2[i][3]);
        float4 o0 = make_float4(p0.x + bv0.x, p0.y + bv0.y, p1.x + bv0.z, p1.y + bv0.w);
        float4 o1 = make_float4(p2.x + bv1.x, p2.y + bv1.y, p3.x + bv1.z, p3.y + bv1.w);
        *(float4*)&g_xproj[row * HCC + n0 + tx * 8]     = o0;
        *(float4*)&g_xproj[row * HCC + n0 + tx * 8 + 4] = o1;
    }
}

// ---------------------------------------------------------------------------
// Recurrence: distributed-push + mbarrier + packed FFMA2.
// Cluster rank = cg (0..7). CTA(bg,cg): batches {2bg,2bg+1}, ch [64cg,+64).
//  - Wh slice pre-packed in registers as 32 ulonglong2 (f32x2 k-pairs).
//  - Dot: h staged per-batch, read as ulonglong2 (LDS.128 = two b64 pairs,
//    zero packing movs); 128 FFMA2/thread (floor ~512 cyc vs 1024).
//  - Epilogue (t<128): reduce, tanh, write hn to local hnl + global ys.
//  - Push: warp w sends the whole 128-float slice to rank w (one remote
//    st.v4 + one release-arrive PER THREAD, parallel across warps — this is
//    what R10 got wrong). mbar expect = 8 src x 32 = 256 arrives.
//  - Consumer: mbarrier.try_wait.parity.acquire.cluster (~60-90 cyc),
//    data already local. Double buffer + parity = backpressure.
// ---------------------------------------------------------------------------
__global__ __launch_bounds__(RTH, 1) __cluster_dims__(CSIZE, 1, 1)
void rec_kernel(const float* __restrict__ Wh, const float* __restrict__ bh,
                float* __restrict__ out_ys, float* __restrict__ out_hs,
                int write_internal)
{
    __shared__ float hs[2][BPG * HCC];   // staged h, double buffered (8 KB)
    __shared__ float red[4 * 128];       // k-split partials [ks][b*64+c]
    __shared__ float hnl[128];           // this CTA's new h slice
    __shared__ __align__(8) unsigned long long mbar[2];

    const int t    = threadIdx.x;
    const int bid  = blockIdx.x;
    const int bg   = bid >> 3;
    const int cg   = bid & 7;
    const int b0   = bg * BPG;
    const int c0   = cg * CPG;
    const int w    = t >> 5;
    const int lane = t & 31;
    const int ks   = w >> 1;                  // k-slice 0..3 (128 k each)
    const int c    = ((w & 1) << 5) + lane;   // channel-in-group 0..63

    float* ysp = write_internal ? (float*)g_ys0 : out_ys;

    // Step-invariant weights -> registers, pre-packed as f32x2 pairs.
    ulonglong2 wr2[32];
    {
        const ulonglong2* wsrc =
            (const ulonglong2*)(Wh + (size_t)(c0 + c) * HCC + ks * 128);
#pragma unroll
        for (int j = 0; j < 32; j++) wr2[j] = wsrc[j];
    }

    const uint32_t mb0  = smem_u32(&mbar[0]);
    const uint32_t mb1  = smem_u32(&mbar[1]);
    const uint32_t hsb0 = smem_u32(&hs[0][0]);
    const uint32_t hsb1 = smem_u32(&hs[1][0]);

    if (t == 0) { mbar_init(mb0, 256); mbar_init(mb1, 256); }
    // h0 = 0: zero local staging buffer 0 (no comm needed for step 0).
#pragma unroll
    for (int i = t; i < BPG * HCC; i += RTH) hs[0][i] = 0.f;
    __syncthreads();
    CL_SYNC();   // all mbarriers initialized before any push can land

    // Push-side addresses (per thread): warp w targets rank w; lane owns
    // float4 #lane of the slice -> b = lane>>4, ch4 = lane&15.
    const uint32_t doff = (uint32_t)((((lane >> 4) * HCC) + c0 + 4 * (lane & 15)) * 4);
    const uint32_t rh0  = mapa_u32(hsb0, (uint32_t)w) + doff;
    const uint32_t rh1  = mapa_u32(hsb1, (uint32_t)w) + doff;
    const uint32_t rm0  = mapa_u32(mb0, (uint32_t)w);
    const uint32_t rm1  = mapa_u32(mb1, (uint32_t)w);

    // Epilogue constants (t<128): output (b = t>>6, ch = t&63).
    float bhv = 0.f;
    if (t < 128) bhv = __ldg(bh + c0 + (t & 63));

    int ph0 = 0, ph1 = 0;

    for (int s = 0; s < TT; s++) {
        // Prefetch xproj (independent of the h chain; issued before the wait).
        float xpv = 0.f;
        if (t < 128)
            xpv = __ldg(&g_xproj[(size_t)s * (BB * HCC) +
                                 (size_t)(b0 + (t >> 6)) * HCC + c0 + (t & 63)]);

        if (s > 0) {
            if (s & 1) { mbar_wait_parity(mb1, (uint32_t)ph1); ph1 ^= 1; }
            else       { mbar_wait_parity(mb0, (uint32_t)ph0); ph0 ^= 1; }
        }

        // Dot: channel c fixed, k in [128ks,128ks+128), both batches, FFMA2.
        const ulonglong2* hb0 = (const ulonglong2*)(hs[s & 1] + (ks << 7));
        const ulonglong2* hb1 = (const ulonglong2*)(hs[s & 1] + HCC + (ks << 7));
        unsigned long long a0a = 0ULL, a0b = 0ULL, a1a = 0ULL, a1b = 0ULL;
#pragma unroll
        for (int j = 0; j < 32; j++) {
            ulonglong2 wv = wr2[j];
            ulonglong2 h0 = hb0[j];
            ulonglong2 h1 = hb1[j];
            fma2(a0a, wv.x, h0.x);
            fma2(a0b, wv.y, h0.y);
            fma2(a1a, wv.x, h1.x);
            fma2(a1b, wv.y, h1.y);
        }
        float2 s0 = unpk(add2(a0a, a0b));
        float2 s1 = unpk(add2(a1a, a1b));
        red[(ks << 7) + c]      = s0.x + s0.y;
        red[(ks << 7) + 64 + c] = s1.x + s1.y;
        __syncthreads();

        // Epilogue: 128 threads, one output each.
        if (t < 128) {
            float sum = xpv + bhv;
#pragma unroll
            for (int k = 0; k < 4; k++) sum += red[(k << 7) + t];
            float hn = tanhf(sum);
            hnl[t] = hn;
            ysp[(size_t)s * (BB * HCC) +
                (size_t)(b0 + (t >> 6)) * HCC + c0 + (t & 63)] = hn;
            if (s == TT - 1)
                out_hs[(size_t)(b0 + (t >> 6)) * HCC + c0 + (t & 63)] = hn;
        }
        __syncthreads();

        // Push: every warp ships the full slice to its rank, in parallel.
        if (s + 1 < TT) {
            float4 v = ((const float4*)hnl)[lane];
            if ((s + 1) & 1) { st_cluster_f4(rh1, v); mbar_arrive_remote(rm1); }
            else             { st_cluster_f4(rh0, v); mbar_arrive_remote(rm0); }
        }
    }

    CL_SYNC();   // no CTA exits while peers' remote ops may be in flight
}

// ---------------------------------------------------------------------------
// Output layout: [hs (L,B,HC) | inp (T,B,HC)]
// ---------------------------------------------------------------------------
extern "C" void kernel_launch(void* const* d_in, const int* in_sizes, int n_in,
                              void* d_out, int out_size) {
    const float* x  = (const float*)d_in[0];
    const float* Wi = (const float*)d_in[1];
    const float* bi = (const float*)d_in[2];
    const float* Wh = (const float*)d_in[3];
    const float* bh = (const float*)d_in[4];
    float* out = (float*)d_out;

    dim3 pg(HCC / PBN, (TT * BB) / PBM);  // (4, 512)

    // Layer 0
    proj_kernel<<<pg, 256>>>(x, Wi, bi, 0);
    rec_kernel<<<NCTA, RTH>>>(Wh, bh, nullptr, out, 1);

    // Layer 1
    proj_kernel<<<pg, 256>>>(x, Wi + HCC * ICC, bi + HCC, 1);
    rec_kernel<<<NCTA, RTH>>>(Wh + HCC * HCC, bh + HCC,
                              out + (size_t)LLL * BB * HCC,  // inp region
                              out + BB * HCC,                // hs[1]
                              0);
}

// round 13
// speedup vs baseline: 1.6734x; 1.0347x over previous
#include <cuda_runtime.h>
#include <math.h>
#include <stdint.h>

// Problem constants
#define TT   2048
#define BB   32
#define ICC  512
#define HCC  512
#define LLL  2

// Recurrence: cluster = 8 CTAs = one batch group (2 batches); CTA owns 64 ch.
#define CSIZE 8
#define NCTA  128
#define RTH   256
#define BPG   2
#define CPG   64

// Projection GEMM config
#define PBM 128
#define PBN 128
#define PBK 16
#define PLD (PBM + 4)

// ---------------------------------------------------------------------------
// Scratch (static device globals: allocation-free per harness rules)
// ---------------------------------------------------------------------------
__device__ float g_xproj[(size_t)TT * BB * HCC];
__device__ float g_ys0[(size_t)TT * BB * HCC];

// ---------------------------------------------------------------------------
// Packed f32x2 helpers (FFMA2: ptxas never auto-fuses; PTX-only pattern)
// ---------------------------------------------------------------------------
__device__ __forceinline__ void fma2(unsigned long long& acc,
                                     unsigned long long a, unsigned long long b) {
    asm("fma.rn.f32x2 %0, %1, %2, %0;" : "+l"(acc) : "l"(a), "l"(b));
}
__device__ __forceinline__ unsigned long long dup2(float x) {
    unsigned long long d;
    asm("mov.b64 %0, {%1, %1};" : "=l"(d) : "f"(x));
    return d;
}
__device__ __forceinline__ unsigned long long add2(unsigned long long a,
                                                   unsigned long long b) {
    unsigned long long r;
    asm("add.rn.f32x2 %0, %1, %2;" : "=l"(r) : "l"(a), "l"(b));
    return r;
}
__device__ __forceinline__ float2 unpk(unsigned long long v) {
    float2 r;
    asm("mov.b64 {%0, %1}, %2;" : "=f"(r.x), "=f"(r.y) : "l"(v));
    return r;
}

// ---------------------------------------------------------------------------
// Cluster / mbarrier helpers (field-verified in earlier rounds)
// ---------------------------------------------------------------------------
__device__ __forceinline__ uint32_t smem_u32(const void* p) {
    uint32_t a;
    asm("{ .reg .u64 t; cvta.to.shared.u64 t, %1; cvt.u32.u64 %0, t; }"
        : "=r"(a) : "l"(p));
    return a;
}
__device__ __forceinline__ uint32_t mapa_u32(uint32_t a, uint32_t rank) {
    uint32_t r;
    asm("mapa.shared::cluster.u32 %0, %1, %2;" : "=r"(r) : "r"(a), "r"(rank));
    return r;
}
__device__ __forceinline__ void st_cluster_f4(uint32_t a, float4 v) {
    asm volatile("st.shared::cluster.v4.f32 [%0], {%1,%2,%3,%4};"
                 :: "r"(a), "f"(v.x), "f"(v.y), "f"(v.z), "f"(v.w) : "memory");
}
__device__ __forceinline__ void mbar_init(uint32_t a, uint32_t cnt) {
    asm volatile("mbarrier.init.shared.b64 [%0], %1;" :: "r"(a), "r"(cnt) : "memory");
}
__device__ __forceinline__ void mbar_arrive_remote(uint32_t a) {
    asm volatile("mbarrier.arrive.release.cluster.shared::cluster.b64 _, [%0];"
                 :: "r"(a) : "memory");
}
__device__ __forceinline__ void mbar_wait_parity(uint32_t a, uint32_t parity) {
    uint32_t done;
    asm volatile(
        "{\n\t.reg .pred p;\n\t"
        "mbarrier.try_wait.parity.acquire.cluster.shared::cta.b64 p, [%1], %2;\n\t"
        "selp.b32 %0, 1, 0, p;\n\t}"
        : "=r"(done) : "r"(a), "r"(parity) : "memory");
    if (!done) {
        asm volatile(
            "{\n\t.reg .pred P1;\n\t"
            "W_%=:\n\t"
            "mbarrier.try_wait.parity.acquire.cluster.shared::cta.b64 P1, [%0], %1, 0x989680;\n\t"
            "@P1 bra.uni D_%=;\n\t"
            "bra.uni W_%=;\n\t"
            "D_%=:\n\t}"
            :: "r"(a), "r"(parity) : "memory");
    }
}
#define CL_SYNC() do { \
    asm volatile("barrier.cluster.arrive.aligned;" ::: "memory"); \
    asm volatile("barrier.cluster.wait.aligned;"   ::: "memory"); } while (0)

// ---------------------------------------------------------------------------
// Projection GEMM with packed FFMA2 (unchanged from R11)
// ---------------------------------------------------------------------------
__global__ __launch_bounds__(256, 2)
void proj_kernel(const float* __restrict__ Xin, const float* __restrict__ Wp,
                 const float* __restrict__ bp, int use_internal)
{
    const float* A = use_internal ? (const float*)g_ys0 : Xin;
    __shared__ float As[PBK][PLD];
    __shared__ float Bs[PBK][PLD];

    const int t  = threadIdx.x;
    const int m0 = blockIdx.y * PBM;
    const int n0 = blockIdx.x * PBN;
    const int lr = t >> 1;
    const int lc = (t & 1) << 3;
    const int tx = t & 15;
    const int ty = t >> 4;

    unsigned long long acc2[8][4];
#pragma unroll
    for (int i = 0; i < 8; i++)
#pragma unroll
        for (int j = 0; j < 4; j++) acc2[i][j] = 0ULL;

    const float* Ag = A  + (size_t)(m0 + lr) * ICC;
    const float* Bg = Wp + (size_t)(n0 + lr) * ICC;

    for (int k0 = 0; k0 < ICC; k0 += PBK) {
        float4 a0 = __ldg((const float4*)(Ag + k0 + lc));
        float4 a1 = __ldg((const float4*)(Ag + k0 + lc + 4));
        float4 b0 = __ldg((const float4*)(Bg + k0 + lc));
        float4 b1 = __ldg((const float4*)(Bg + k0 + lc + 4));
        As[lc+0][lr] = a0.x; As[lc+1][lr] = a0.y; As[lc+2][lr] = a0.z; As[lc+3][lr] = a0.w;
        As[lc+4][lr] = a1.x; As[lc+5][lr] = a1.y; As[lc+6][lr] = a1.z; As[lc+7][lr] = a1.w;
        Bs[lc+0][lr] = b0.x; Bs[lc+1][lr] = b0.y; Bs[lc+2][lr] = b0.z; Bs[lc+3][lr] = b0.w;
        Bs[lc+4][lr] = b1.x; Bs[lc+5][lr] = b1.y; Bs[lc+6][lr] = b1.z; Bs[lc+7][lr] = b1.w;
        __syncthreads();
#pragma unroll
        for (int k = 0; k < PBK; k++) {
            float4 am0 = *(const float4*)&As[k][ty * 8];
            float4 am1 = *(const float4*)&As[k][ty * 8 + 4];
            ulonglong2 bu0 = *(const ulonglong2*)&Bs[k][tx * 8];
            ulonglong2 bu1 = *(const ulonglong2*)&Bs[k][tx * 8 + 4];
            float am[8] = {am0.x, am0.y, am0.z, am0.w, am1.x, am1.y, am1.z, am1.w};
#pragma unroll
            for (int i = 0; i < 8; i++) {
                unsigned long long ad = dup2(am[i]);
                fma2(acc2[i][0], ad, bu0.x);
                fma2(acc2[i][1], ad, bu0.y);
                fma2(acc2[i][2], ad, bu1.x);
                fma2(acc2[i][3], ad, bu1.y);
            }
        }
        __syncthreads();
    }

    float4 bv0 = __ldg((const float4*)(bp + n0 + tx * 8));
    float4 bv1 = __ldg((const float4*)(bp + n0 + tx * 8 + 4));
#pragma unroll
    for (int i = 0; i < 8; i++) {
        size_t row = (size_t)(m0 + ty * 8 + i);
        float2 p0 = unpk(acc2[i][0]);
        float2 p1 = unpk(acc2[i][1]);
        float2 p2 = unpk(acc2[i][2]);
        float2 p3 = unpk(acc2[i][3]);
        float4 o0 = make_float4(p0.x + bv0.x, p0.y + bv0.y, p1.x + bv0.z, p1.y + bv0.w);
        float4 o1 = make_float4(p2.x + bv1.x, p2.y + bv1.y, p3.x + bv1.z, p3.y + bv1.w);
        *(float4*)&g_xproj[row * HCC + n0 + tx * 8]     = o0;
        *(float4*)&g_xproj[row * HCC + n0 + tx * 8 + 4] = o1;
    }
}

// ---------------------------------------------------------------------------
// Recurrence: distributed push + AGGREGATED arrives + FFMA2.
// Delta vs R11 (isolated): (a) one release-arrive per warp (8/step/barrier,
// expect=8) instead of per-lane (256) — kills arrive serialization at the
// target mbarrier; cumulativity over __syncwarp covers all lanes' stores.
// (b) global ys/out stores moved AFTER the push (off the producer chain).
// ---------------------------------------------------------------------------
__global__ __launch_bounds__(RTH, 1) __cluster_dims__(CSIZE, 1, 1)
void rec_kernel(const float* __restrict__ Wh, const float* __restrict__ bh,
                float* __restrict__ out_ys, float* __restrict__ out_hs,
                int write_internal)
{
    __shared__ float hs[2][BPG * HCC];   // staged h, double buffered (8 KB)
    __shared__ float red[4 * 128];       // k-split partials [ks][b*64+c]
    __shared__ float hnl[128];           // this CTA's new h slice
    __shared__ __align__(8) unsigned long long mbar[2];

    const int t    = threadIdx.x;
    const int bid  = blockIdx.x;
    const int bg   = bid >> 3;
    const int cg   = bid & 7;
    const int b0   = bg * BPG;
    const int c0   = cg * CPG;
    const int w    = t >> 5;
    const int lane = t & 31;
    const int ks   = w >> 1;                  // k-slice 0..3 (128 k each)
    const int c    = ((w & 1) << 5) + lane;   // channel-in-group 0..63

    float* ysp = write_internal ? (float*)g_ys0 : out_ys;

    // Step-invariant weights -> registers, pre-packed as f32x2 pairs.
    ulonglong2 wr2[32];
    {
        const ulonglong2* wsrc =
            (const ulonglong2*)(Wh + (size_t)(c0 + c) * HCC + ks * 128);
#pragma unroll
        for (int j = 0; j < 32; j++) wr2[j] = wsrc[j];
    }

    const uint32_t mb0  = smem_u32(&mbar[0]);
    const uint32_t mb1  = smem_u32(&mbar[1]);
    const uint32_t hsb0 = smem_u32(&hs[0][0]);
    const uint32_t hsb1 = smem_u32(&hs[1][0]);

    if (t == 0) { mbar_init(mb0, CSIZE); mbar_init(mb1, CSIZE); }  // 1 arrive/src CTA
    // h0 = 0: zero local staging buffer 0 (no comm needed for step 0).
#pragma unroll
    for (int i = t; i < BPG * HCC; i += RTH) hs[0][i] = 0.f;
    __syncthreads();
    CL_SYNC();   // all mbarriers initialized before any push can land

    // Push-side addresses (per thread): warp w targets rank w; lane owns
    // float4 #lane of the slice -> b = lane>>4, ch4 = lane&15.
    const uint32_t doff = (uint32_t)((((lane >> 4) * HCC) + c0 + 4 * (lane & 15)) * 4);
    const uint32_t rh0  = mapa_u32(hsb0, (uint32_t)w) + doff;
    const uint32_t rh1  = mapa_u32(hsb1, (uint32_t)w) + doff;
    const uint32_t rm0  = mapa_u32(mb0, (uint32_t)w);
    const uint32_t rm1  = mapa_u32(mb1, (uint32_t)w);

    // Epilogue constants (t<128): output (b = t>>6, ch = t&63).
    float bhv = 0.f;
    if (t < 128) bhv = __ldg(bh + c0 + (t & 63));

    int ph0 = 0, ph1 = 0;

    for (int s = 0; s < TT; s++) {
        // Prefetch xproj (independent of the h chain; issued before the wait).
        float xpv = 0.f;
        if (t < 128)
            xpv = __ldg(&g_xproj[(size_t)s * (BB * HCC) +
                                 (size_t)(b0 + (t >> 6)) * HCC + c0 + (t & 63)]);

        if (s > 0) {
            if (s & 1) { mbar_wait_parity(mb1, (uint32_t)ph1); ph1 ^= 1; }
            else       { mbar_wait_parity(mb0, (uint32_t)ph0); ph0 ^= 1; }
        }

        // Dot: channel c fixed, k in [128ks,128ks+128), both batches, FFMA2.
        const ulonglong2* hb0 = (const ulonglong2*)(hs[s & 1] + (ks << 7));
        const ulonglong2* hb1 = (const ulonglong2*)(hs[s & 1] + HCC + (ks << 7));
        unsigned long long a0a = 0ULL, a0b = 0ULL, a1a = 0ULL, a1b = 0ULL;
#pragma unroll
        for (int j = 0; j < 32; j++) {
            ulonglong2 wv = wr2[j];
            ulonglong2 h0 = hb0[j];
            ulonglong2 h1 = hb1[j];
            fma2(a0a, wv.x, h0.x);
            fma2(a0b, wv.y, h0.y);
            fma2(a1a, wv.x, h1.x);
            fma2(a1b, wv.y, h1.y);
        }
        float2 s0 = unpk(add2(a0a, a0b));
        float2 s1 = unpk(add2(a1a, a1b));
        red[(ks << 7) + c]      = s0.x + s0.y;
        red[(ks << 7) + 64 + c] = s1.x + s1.y;
        __syncthreads();

        // Epilogue part 1: compute hn, stage locally (global stores deferred).
        float hn = 0.f;
        if (t < 128) {
            float sum = xpv + bhv;
#pragma unroll
            for (int k = 0; k < 4; k++) sum += red[(k << 7) + t];
            hn = tanhf(sum);
            hnl[t] = hn;
        }
        __syncthreads();

        // Push: warp w ships the whole 128-float slice to rank w (32 parallel
        // remote st.v4), then ONE aggregated release-arrive per warp.
        if (s + 1 < TT) {
            float4 v = ((const float4*)hnl)[lane];
            if ((s + 1) & 1) {
                st_cluster_f4(rh1, v);
                __syncwarp();
                if (lane == 0) mbar_arrive_remote(rm1);
            } else {
                st_cluster_f4(rh0, v);
                __syncwarp();
                if (lane == 0) mbar_arrive_remote(rm0);
            }
        }

        // Epilogue part 2 (off critical path): global stores.
        if (t < 128) {
            ysp[(size_t)s * (BB * HCC) +
                (size_t)(b0 + (t >> 6)) * HCC + c0 + (t & 63)] = hn;
            if (s == TT - 1)
                out_hs[(size_t)(b0 + (t >> 6)) * HCC + c0 + (t & 63)] = hn;
        }
    }

    CL_SYNC();   // no CTA exits while peers' remote ops may be in flight
}

// ---------------------------------------------------------------------------
// Output layout: [hs (L,B,HC) | inp (T,B,HC)]
// ---------------------------------------------------------------------------
extern "C" void kernel_launch(void* const* d_in, const int* in_sizes, int n_in,
                              void* d_out, int out_size) {
    const float* x  = (const float*)d_in[0];
    const float* Wi = (const float*)d_in[1];
    const float* bi = (const float*)d_in[2];
    const float* Wh = (const float*)d_in[3];
    const float* bh = (const float*)d_in[4];
    float* out = (float*)d_out;

    dim3 pg(HCC / PBN, (TT * BB) / PBM);  // (4, 512)

    // Layer 0
    proj_kernel<<<pg, 256>>>(x, Wi, bi, 0);
    rec_kernel<<<NCTA, RTH>>>(Wh, bh, nullptr, out, 1);

    // Layer 1
    proj_kernel<<<pg, 256>>>(x, Wi + HCC * ICC, bi + HCC, 1);
    rec_kernel<<<NCTA, RTH>>>(Wh + HCC * HCC, bh + HCC,
                              out + (size_t)LLL * BB * HCC,  // inp region
                              out + BB * HCC,                // hs[1]
                              0);
}